// round 7
// baseline (speedup 1.0000x reference)
#include <cuda_runtime.h>
#include <cuda_bf16.h>
#include <cstdint>

#define NQ 8
#define MQ 512
#define DQ 64
#define BQ 8192
#define BT 32
#define THREADS 256

constexpr int EMB_S = 72;    // bf16 element stride per emb row (conflict-free)
constexpr int LS_S  = 520;   // f32/u32 element stride for logits/samples rows

constexpr size_t OFF_KL     = (size_t)BQ * NQ * DQ;   // 4194304
constexpr size_t OFF_PPL    = OFF_KL + 1;
constexpr size_t OFF_LOGITS = OFF_KL + 2;

constexpr int SM_EH  = 0;
constexpr int SM_EL  = SM_EH  + MQ * EMB_S * 2;   // 73728
constexpr int SM_LS  = SM_EL  + MQ * EMB_S * 2;   // 147456
constexpr int SM_XS  = SM_LS  + BT * LS_S * 4;    // 214016
constexpr int SM_XL  = SM_XS  + BT * EMB_S * 2;   // 218624
constexpr int SM_ESQ = SM_XL  + BT * EMB_S * 2;   // 223232
constexpr int SM_AVG = SM_ESQ + MQ * 4;           // 225280
constexpr int SM_RED = SM_AVG + MQ * 4;           // 227328
constexpr int SMEM_BYTES = SM_RED + 64;           // 227392

#define LOGM 6.2383246250395075f

__device__ float g_esq[NQ * MQ];
__device__ float g_avg[NQ * MQ];
__device__ float g_kl;

__device__ __forceinline__ float wredmax(float v) {
    #pragma unroll
    for (int o = 16; o; o >>= 1) v = fmaxf(v, __shfl_xor_sync(0xffffffffu, v, o));
    return v;
}
__device__ __forceinline__ float wredsum(float v) {
    #pragma unroll
    for (int o = 16; o; o >>= 1) v += __shfl_xor_sync(0xffffffffu, v, o);
    return v;
}

// Unbiased exp for f in ~[-0.7, 0]: degree-9 Taylor (truncation < 1e-8 rel,
// no MUFU systematic bias). KL is a huge cancellation; MUFU ex2/lg2 bias is
// amplified thousands of times into the KL relative error, so the KL softmax
// must avoid it.
__device__ __forceinline__ float exp_taylor9(float f) {
    float p = 2.75573192e-6f;               // 1/9!
    p = fmaf(p, f, 2.48015873e-5f);         // 1/8!
    p = fmaf(p, f, 1.98412698e-4f);         // 1/7!
    p = fmaf(p, f, 1.38888889e-3f);         // 1/6!
    p = fmaf(p, f, 8.33333333e-3f);         // 1/5!
    p = fmaf(p, f, 4.16666667e-2f);         // 1/4!
    p = fmaf(p, f, 1.66666667e-1f);         // 1/3!
    p = fmaf(p, f, 0.5f);
    p = fmaf(p, f, 1.0f);
    p = fmaf(p, f, 1.0f);
    return p;
}

__device__ __forceinline__ void mma16816(float* c, const uint32_t* a, const uint32_t* b) {
    asm volatile(
        "mma.sync.aligned.m16n8k16.row.col.f32.bf16.bf16.f32 "
        "{%0,%1,%2,%3}, {%4,%5,%6,%7}, {%8,%9}, {%0,%1,%2,%3};\n"
        : "+f"(c[0]), "+f"(c[1]), "+f"(c[2]), "+f"(c[3])
        : "r"(a[0]), "r"(a[1]), "r"(a[2]), "r"(a[3]), "r"(b[0]), "r"(b[1]));
}

// ---------------------------------------------------------------------------
// Init: per-(n,m) |e|^2 (warp-per-row, coalesced), zero accumulators.
// ---------------------------------------------------------------------------
__global__ void vq_init(const float* __restrict__ emb) {
    const int tid  = threadIdx.x;
    const int lane = tid & 31;
    const int w    = tid >> 5;
    const int row  = blockIdx.x * 8 + w;          // 0 .. 4095
    const float* e = emb + (size_t)row * DQ;
    const float v0 = e[lane];
    const float v1 = e[lane + 32];
    float s = wredsum(fmaf(v0, v0, v1 * v1));
    if (lane == 0) g_esq[row] = s;
    if (tid < 8) g_avg[blockIdx.x * 8 + tid] = 0.f;
    if (blockIdx.x == 0 && tid == 0) g_kl = 0.f;
}

// ---------------------------------------------------------------------------
// Main fused kernel: one CTA = (n, 32 rows of b).
// Phase 1: logits = 2*x.e - |e|^2 via SPLIT-bf16 mma (xh*eh + xh*el + xl*eh)
//          -> ~fp32-accurate logits (KL is hypersensitive to logit noise).
// Phase 2: softmax -> log_probs (ret_logits), KL (bias-free exp/log path,
//          shifted-moment form), gumbel softmax -> samples (bf16 hi/lo).
// Phase 3: quantized = samples @ emb via split-bf16 mma.
// ---------------------------------------------------------------------------
__global__ void __launch_bounds__(THREADS, 1)
vq_main(const float* __restrict__ x, const float* __restrict__ emb,
        const float* __restrict__ u, const float* __restrict__ tau,
        float* __restrict__ out) {
    extern __shared__ char smem[];
    __nv_bfloat16* EH  = (__nv_bfloat16*)(smem + SM_EH);
    __nv_bfloat16* EL  = (__nv_bfloat16*)(smem + SM_EL);
    float*         LS  = (float*)(smem + SM_LS);
    __nv_bfloat16* XS  = (__nv_bfloat16*)(smem + SM_XS);
    __nv_bfloat16* XL  = (__nv_bfloat16*)(smem + SM_XL);
    float*         ESQ = (float*)(smem + SM_ESQ);
    float*         AVG = (float*)(smem + SM_AVG);
    float*         RED = (float*)(smem + SM_RED);

    const int n   = blockIdx.y;
    const int b0  = blockIdx.x * BT;
    const int tid = threadIdx.x;
    const int lane = tid & 31;
    const int w    = tid >> 5;
    const int g    = lane >> 2;
    const int tg   = lane & 3;

    // ---- Phase 0: stage emb + x as hi/lo bf16 pairs, e_sq; zero AVG ----
    const float* embn = emb + (size_t)n * MQ * DQ;
    for (int i = tid; i < MQ * DQ; i += THREADS) {
        const int m = i >> 6, d = i & 63;
        float v = embn[i];
        __nv_bfloat16 h = __float2bfloat16(v);
        float lo = v - __bfloat162float(h);
        EH[m * EMB_S + d] = h;
        EL[m * EMB_S + d] = __float2bfloat16(lo);
    }
    for (int i = tid; i < BT * DQ; i += THREADS) {
        const int r = i >> 6, d = i & 63;
        float v = x[(size_t)(b0 + r) * (NQ * DQ) + n * DQ + d];
        __nv_bfloat16 h = __float2bfloat16(v);
        float lo = v - __bfloat162float(h);
        XS[r * EMB_S + d] = h;
        XL[r * EMB_S + d] = __float2bfloat16(lo);
    }
    for (int i = tid; i < MQ; i += THREADS) {
        ESQ[i] = g_esq[n * MQ + i];
        AVG[i] = 0.f;
    }
    __syncthreads();

    // ---- Phase 1: GEMM1 (32 x 512, K=64), split-bf16 mma ----
    {
        const int rt = w & 1;            // row tile: rows rt*16 .. +15
        const int cb = w >> 1;           // col block: cols cb*128 .. +127
        const int r0 = rt * 16;
        uint32_t ah[4][4], al[4][4];
        #pragma unroll
        for (int ks = 0; ks < 4; ks++) {
            const int kb = ks * 16 + tg * 2;
            ah[ks][0] = *(const uint32_t*)&XS[(r0 + g) * EMB_S + kb];
            ah[ks][1] = *(const uint32_t*)&XS[(r0 + g + 8) * EMB_S + kb];
            ah[ks][2] = *(const uint32_t*)&XS[(r0 + g) * EMB_S + kb + 8];
            ah[ks][3] = *(const uint32_t*)&XS[(r0 + g + 8) * EMB_S + kb + 8];
            al[ks][0] = *(const uint32_t*)&XL[(r0 + g) * EMB_S + kb];
            al[ks][1] = *(const uint32_t*)&XL[(r0 + g + 8) * EMB_S + kb];
            al[ks][2] = *(const uint32_t*)&XL[(r0 + g) * EMB_S + kb + 8];
            al[ks][3] = *(const uint32_t*)&XL[(r0 + g + 8) * EMB_S + kb + 8];
        }
        #pragma unroll
        for (int t = 0; t < 16; t++) {
            const int n0 = cb * 128 + t * 8;
            float c[4] = {0.f, 0.f, 0.f, 0.f};
            #pragma unroll
            for (int ks = 0; ks < 4; ks++) {
                const int kb = ks * 16 + tg * 2;
                uint32_t bh[2], bl[2];
                bh[0] = *(const uint32_t*)&EH[(n0 + g) * EMB_S + kb];
                bh[1] = *(const uint32_t*)&EH[(n0 + g) * EMB_S + kb + 8];
                bl[0] = *(const uint32_t*)&EL[(n0 + g) * EMB_S + kb];
                bl[1] = *(const uint32_t*)&EL[(n0 + g) * EMB_S + kb + 8];
                mma16816(c, ah[ks], bh);
                mma16816(c, ah[ks], bl);
                mma16816(c, al[ks], bh);
            }
            const int col = n0 + tg * 2;
            LS[(r0 + g) * LS_S + col]         = 2.f * c[0] - ESQ[col];
            LS[(r0 + g) * LS_S + col + 1]     = 2.f * c[1] - ESQ[col + 1];
            LS[(r0 + g + 8) * LS_S + col]     = 2.f * c[2] - ESQ[col];
            LS[(r0 + g + 8) * LS_S + col + 1] = 2.f * c[3] - ESQ[col + 1];
        }
    }
    __syncthreads();

    // ---- Phase 2: per-row softmax, ret_logits, KL, gumbel softmax, samples ----
    {
        const float invtau = 1.0f / tau[0];
        float kl_acc = 0.f;
        float rowacc[16];
        #pragma unroll
        for (int i = 0; i < 16; i++) rowacc[i] = 0.f;

        // Pipeline: preload u for row rr=0.
        const float* urow0 = u + ((size_t)n * BQ + b0 + w * 4) * MQ;
        float ur[16];
        #pragma unroll
        for (int i = 0; i < 16; i++) ur[i] = __ldcs(&urow0[lane + i * 32]);

        for (int rr = 0; rr < 4; rr++) {
            const int r = w * 4 + rr;
            const size_t brow = (size_t)b0 + r;

            float gmb[16];
            #pragma unroll
            for (int i = 0; i < 16; i++) gmb[i] = -__logf(-__logf(ur[i]));

            if (rr < 3) {
                const float* unext = urow0 + (size_t)(rr + 1) * MQ;
                #pragma unroll
                for (int i = 0; i < 16; i++) ur[i] = __ldcs(&unext[lane + i * 32]);
            }

            float l[16];
            #pragma unroll
            for (int i = 0; i < 16; i++) l[i] = LS[r * LS_S + lane + i * 32];

            // Gumbel-perturbed logits (logZ shift cancels in softmax).
            float t2[16];
            #pragma unroll
            for (int i = 0; i < 16; i++) t2[i] = (l[i] + gmb[i]) * invtau;

            float mx = l[0];
            #pragma unroll
            for (int i = 1; i < 16; i++) mx = fmaxf(mx, l[i]);
            mx = wredmax(mx);

            float mx2 = t2[0];
            #pragma unroll
            for (int i = 1; i < 16; i++) mx2 = fmaxf(mx2, t2[i]);
            mx2 = wredmax(mx2);

            // KL softmax: bias-free exp (Taylor), f in [-~0.1, 0].
            // Accumulate the SHIFTED first moment sum t*f (not t*l): the
            // KL cancellation then happens between two ~0.1-magnitude terms
            // instead of two ~6.24-magnitude terms (~60x less fp32 noise).
            float s1l = 0.f, stfl = 0.f;
            #pragma unroll
            for (int i = 0; i < 16; i++) {
                const float f = l[i] - mx;
                const float t = exp_taylor9(f);
                s1l += t;
                stfl = fmaf(t, f, stfl);
            }

            float s2l = 0.f;
            #pragma unroll
            for (int i = 0; i < 16; i++) { t2[i] = __expf(t2[i] - mx2); s2l += t2[i]; }

            const float s1  = wredsum(s1l);
            const float stf = wredsum(stfl);
            const float inv2 = 1.0f / wredsum(s2l);

            // log(s1) = log(512) + log1p(s1/512 - 1): exact exponent shift +
            // Sterbenz-exact subtraction kills __logf's systematic bias.
            const float lg1p = log1pf(fmaf(s1, 1.0f / 512.0f, -1.0f));
            const float logZ = mx + LOGM + lg1p;
            // KL_row = E_p[l] - logZ + logM = stf/s1 - lg1p
            kl_acc += stf / s1 - lg1p;

            float* outlp = out + OFF_LOGITS + (brow * NQ + n) * MQ;
            #pragma unroll
            for (int i = 0; i < 16; i++) {
                __stcs(&outlp[lane + i * 32], l[i] - logZ);
            }

            uint32_t* SSM = (uint32_t*)LS;
            #pragma unroll
            for (int i = 0; i < 16; i++) {
                const float s = t2[i] * inv2;
                rowacc[i] += s;
                __nv_bfloat16 h = __float2bfloat16(s);
                float lo = s - __bfloat162float(h);
                __nv_bfloat16 hl = __float2bfloat16(lo);
                uint32_t pk = (uint32_t)__bfloat16_as_ushort(h) |
                              ((uint32_t)__bfloat16_as_ushort(hl) << 16);
                SSM[r * LS_S + lane + i * 32] = pk;
            }
        }
        #pragma unroll
        for (int i = 0; i < 16; i++) atomicAdd(&AVG[lane + i * 32], rowacc[i]);
        if (lane == 0) RED[w] = kl_acc;   // kl_acc identical across lanes
    }
    __syncthreads();

    if (tid == 0) {
        float s = 0.f;
        #pragma unroll
        for (int i = 0; i < 8; i++) s += RED[i];
        atomicAdd(&g_kl, s);
    }
    for (int i = tid; i < MQ; i += THREADS) atomicAdd(&g_avg[n * MQ + i], AVG[i]);

    // ---- Phase 3: GEMM2 quantized = samples @ emb, split-bf16 mma ----
    {
        const uint32_t* SSM = (const uint32_t*)LS;
        const uint16_t* EH16 = (const uint16_t*)EH;
        const uint16_t* EL16 = (const uint16_t*)EL;
        const int rt  = w & 1;
        const int dt0 = (w >> 1) * 2;
        const int ra  = rt * 16 + g;
        float c0[4] = {0.f, 0.f, 0.f, 0.f};
        float c1[4] = {0.f, 0.f, 0.f, 0.f};

        #pragma unroll 4
        for (int ks = 0; ks < 32; ks++) {
            const int kb = ks * 16 + tg * 2;
            uint32_t ah[4], al[4];
            #pragma unroll
            for (int j = 0; j < 4; j++) {
                const int row = ra + (j & 1) * 8;
                const int kk  = kb + (j >> 1) * 8;
                const uint32_t p0 = SSM[row * LS_S + kk];
                const uint32_t p1 = SSM[row * LS_S + kk + 1];
                ah[j] = __byte_perm(p0, p1, 0x5410);   // hi halves
                al[j] = __byte_perm(p0, p1, 0x7632);   // lo halves
            }
            #pragma unroll
            for (int dt = 0; dt < 2; dt++) {
                const int dcol = (dt0 + dt) * 8 + g;
                uint32_t bh[2], bl[2];
                bh[0] = (uint32_t)EH16[kb * EMB_S + dcol]       | ((uint32_t)EH16[(kb + 1) * EMB_S + dcol] << 16);
                bh[1] = (uint32_t)EH16[(kb + 8) * EMB_S + dcol] | ((uint32_t)EH16[(kb + 9) * EMB_S + dcol] << 16);
                bl[0] = (uint32_t)EL16[kb * EMB_S + dcol]       | ((uint32_t)EL16[(kb + 1) * EMB_S + dcol] << 16);
                bl[1] = (uint32_t)EL16[(kb + 8) * EMB_S + dcol] | ((uint32_t)EL16[(kb + 9) * EMB_S + dcol] << 16);
                float* cc = dt ? c1 : c0;
                mma16816(cc, ah, bh);
                mma16816(cc, ah, bl);
                mma16816(cc, al, bh);
            }
        }
        #pragma unroll
        for (int dt = 0; dt < 2; dt++) {
            const float* cc = dt ? c1 : c0;
            const int dcol = (dt0 + dt) * 8 + tg * 2;
            const size_t base0 = ((size_t)(b0 + ra) * NQ + n) * DQ + dcol;
            const size_t base1 = ((size_t)(b0 + ra + 8) * NQ + n) * DQ + dcol;
            __stcs(&out[base0],     cc[0]);
            __stcs(&out[base0 + 1], cc[1]);
            __stcs(&out[base1],     cc[2]);
            __stcs(&out[base1 + 1], cc[3]);
        }
    }
}

// ---------------------------------------------------------------------------
// Finalize: KL mean, perplexity sum.
// ---------------------------------------------------------------------------
__global__ void vq_final(float* __restrict__ out) {
    const int tid = threadIdx.x;
    const int w = tid >> 5, lane = tid & 31;
    __shared__ float red[8];
    if (w < 8) {
        float acc = 0.f;
        #pragma unroll
        for (int i = 0; i < 16; i++) {
            float a = g_avg[w * MQ + lane + i * 32] * (1.0f / (float)BQ);
            acc = fmaf(a, __logf(a + 1e-10f), acc);
        }
        acc = wredsum(acc);
        if (lane == 0) red[w] = acc;
    }
    __syncthreads();
    if (tid == 0) {
        float s = 0.f;
        #pragma unroll
        for (int i = 0; i < 8; i++) s += __expf(-red[i]);
        out[OFF_PPL] = s;
        out[OFF_KL]  = g_kl * (1.0f / (float)BQ);
    }
}

extern "C" void kernel_launch(void* const* d_in, const int* in_sizes, int n_in,
                              void* d_out, int out_size) {
    const float* x   = (const float*)d_in[0];
    const float* emb = (const float*)d_in[1];
    const float* u   = (const float*)d_in[2];
    const float* tau = (const float*)d_in[3];
    float* out = (float*)d_out;

    cudaFuncSetAttribute(vq_main, cudaFuncAttributeMaxDynamicSharedMemorySize, SMEM_BYTES);

    vq_init<<<NQ * MQ / 8, 256>>>(emb);
    vq_main<<<dim3(BQ / BT, NQ, 1), THREADS, SMEM_BYTES>>>(x, emb, u, tau, out);
    vq_final<<<1, 256>>>(out);
}

// round 12
// speedup vs baseline: 1.3067x; 1.3067x over previous
#include <cuda_runtime.h>
#include <cuda_bf16.h>
#include <cstdint>

#define NQ 8
#define MQ 512
#define DQ 64
#define BQ 8192
#define BT 32
#define TILES 4
#define THREADS 256

constexpr int EMB_S = 72;    // bf16 element stride per emb row (conflict-free)
constexpr int LS_S  = 520;   // f32/u32 element stride for logits/samples rows

constexpr size_t OFF_KL     = (size_t)BQ * NQ * DQ;   // 4194304
constexpr size_t OFF_PPL    = OFF_KL + 1;
constexpr size_t OFF_LOGITS = OFF_KL + 2;

constexpr int SM_EH  = 0;
constexpr int SM_EL  = SM_EH  + MQ * EMB_S * 2;   // 73728
constexpr int SM_LS  = SM_EL  + MQ * EMB_S * 2;   // 147456 (66560 bytes)
constexpr int SM_XS  = SM_LS  + BT * LS_S * 4;    // 214016
constexpr int SM_XL  = SM_XS  + BT * EMB_S * 2;   // 218624
constexpr int SM_ESQ = SM_XL  + BT * EMB_S * 2;   // 223232
constexpr int SM_AVG = SM_ESQ + MQ * 4;           // 225280
constexpr int SM_RED = SM_AVG + MQ * 4;           // 227328
constexpr int SMEM_BYTES = SM_RED + 64;           // 227392

#define LOGM 6.2383246250395075f

__device__ float g_esq[NQ * MQ];
__device__ float g_avg[NQ * MQ];
__device__ float g_kl;

__device__ __forceinline__ float wredmax(float v) {
    #pragma unroll
    for (int o = 16; o; o >>= 1) v = fmaxf(v, __shfl_xor_sync(0xffffffffu, v, o));
    return v;
}
__device__ __forceinline__ float wredsum(float v) {
    #pragma unroll
    for (int o = 16; o; o >>= 1) v += __shfl_xor_sync(0xffffffffu, v, o);
    return v;
}

// Unbiased exp for f in ~[-0.7, 0]: degree-9 Taylor. KL is a huge
// cancellation; MUFU ex2/lg2 systematic bias would be amplified thousands of
// times into the KL relative error.
__device__ __forceinline__ float exp_taylor9(float f) {
    float p = 2.75573192e-6f;
    p = fmaf(p, f, 2.48015873e-5f);
    p = fmaf(p, f, 1.98412698e-4f);
    p = fmaf(p, f, 1.38888889e-3f);
    p = fmaf(p, f, 8.33333333e-3f);
    p = fmaf(p, f, 4.16666667e-2f);
    p = fmaf(p, f, 1.66666667e-1f);
    p = fmaf(p, f, 0.5f);
    p = fmaf(p, f, 1.0f);
    p = fmaf(p, f, 1.0f);
    return p;
}

// Pack two floats into bf16x2 hi-word + produce the bf16x2 residual word.
__device__ __forceinline__ uint32_t pack2_hilo(float a, float b, uint32_t& lopk) {
    __nv_bfloat16 ha = __float2bfloat16(a), hb = __float2bfloat16(b);
    float la = a - __bfloat162float(ha);
    float lb = b - __bfloat162float(hb);
    lopk = (uint32_t)__bfloat16_as_ushort(__float2bfloat16(la)) |
           ((uint32_t)__bfloat16_as_ushort(__float2bfloat16(lb)) << 16);
    return (uint32_t)__bfloat16_as_ushort(ha) |
           ((uint32_t)__bfloat16_as_ushort(hb) << 16);
}

__device__ __forceinline__ void mma16816(float* c, const uint32_t* a, const uint32_t* b) {
    asm volatile(
        "mma.sync.aligned.m16n8k16.row.col.f32.bf16.bf16.f32 "
        "{%0,%1,%2,%3}, {%4,%5,%6,%7}, {%8,%9}, {%0,%1,%2,%3};\n"
        : "+f"(c[0]), "+f"(c[1]), "+f"(c[2]), "+f"(c[3])
        : "r"(a[0]), "r"(a[1]), "r"(a[2]), "r"(a[3]), "r"(b[0]), "r"(b[1]));
}

// ---------------------------------------------------------------------------
__global__ void vq_init(const float* __restrict__ emb) {
    const int tid  = threadIdx.x;
    const int lane = tid & 31;
    const int w    = tid >> 5;
    const int row  = blockIdx.x * 8 + w;
    const float* e = emb + (size_t)row * DQ;
    const float v0 = e[lane];
    const float v1 = e[lane + 32];
    float s = wredsum(fmaf(v0, v0, v1 * v1));
    if (lane == 0) g_esq[row] = s;
    if (tid < 8) g_avg[blockIdx.x * 8 + tid] = 0.f;
    if (blockIdx.x == 0 && tid == 0) g_kl = 0.f;
}

// ---------------------------------------------------------------------------
// One CTA = (n, 4 consecutive 32-row b-tiles). emb staged ONCE per CTA.
// Per tile, phases identical to the proven 326.9us kernel:
//   Phase 1: logits via split-bf16 mma
//   Phase 2: softmax/KL/ret_logits + gumbel softmax -> packed hi|lo samples
//   Phase 3: quantized via scalar-LDS split-bf16 mma (proven path)
// ---------------------------------------------------------------------------
__global__ void __launch_bounds__(THREADS, 1)
vq_main(const float* __restrict__ x, const float* __restrict__ emb,
        const float* __restrict__ u, const float* __restrict__ tau,
        float* __restrict__ out) {
    extern __shared__ char smem[];
    __nv_bfloat16* EH  = (__nv_bfloat16*)(smem + SM_EH);
    __nv_bfloat16* EL  = (__nv_bfloat16*)(smem + SM_EL);
    float*         LS  = (float*)(smem + SM_LS);
    __nv_bfloat16* XS  = (__nv_bfloat16*)(smem + SM_XS);
    __nv_bfloat16* XL  = (__nv_bfloat16*)(smem + SM_XL);
    float*         ESQ = (float*)(smem + SM_ESQ);
    float*         AVG = (float*)(smem + SM_AVG);
    float*         RED = (float*)(smem + SM_RED);

    const int n   = blockIdx.y;
    const int tid = threadIdx.x;
    const int lane = tid & 31;
    const int w    = tid >> 5;
    const int g    = lane >> 2;
    const int tg   = lane & 3;
    const float invtau = 1.0f / tau[0];

    // ---- stage emb hi/lo + e_sq ONCE (float4 loads, uint2 stores) ----
    const float* embn = emb + (size_t)n * MQ * DQ;
    for (int i = tid * 4; i < MQ * DQ; i += THREADS * 4) {
        const float4 v4 = *(const float4*)&embn[i];
        const int m = i >> 6, d = i & 63;
        uint32_t lo01, lo23;
        const uint32_t h01 = pack2_hilo(v4.x, v4.y, lo01);
        const uint32_t h23 = pack2_hilo(v4.z, v4.w, lo23);
        *(uint2*)&EH[m * EMB_S + d] = make_uint2(h01, h23);
        *(uint2*)&EL[m * EMB_S + d] = make_uint2(lo01, lo23);
    }
    for (int i = tid; i < MQ; i += THREADS) {
        ESQ[i] = g_esq[n * MQ + i];
        AVG[i] = 0.f;
    }

    const int rt  = w & 1;           // row tile (phases 1&3)
    const int cb  = w >> 1;          // phase-1 col block
    const int dt0 = (w >> 1) * 2;    // phase-3 d tiles

    float kl_acc = 0.f;

    for (int t = 0; t < TILES; t++) {
        const int b0 = (blockIdx.x * TILES + t) * BT;

        // ---- stage x tile hi/lo (float4 loads) ----
        for (int i = tid * 4; i < BT * DQ; i += THREADS * 4) {
            const int r = i >> 6, d = i & 63;
            const float4 v4 = *(const float4*)&x[(size_t)(b0 + r) * (NQ * DQ) + n * DQ + d];
            uint32_t lo01, lo23;
            const uint32_t h01 = pack2_hilo(v4.x, v4.y, lo01);
            const uint32_t h23 = pack2_hilo(v4.z, v4.w, lo23);
            *(uint2*)&XS[r * EMB_S + d] = make_uint2(h01, h23);
            *(uint2*)&XL[r * EMB_S + d] = make_uint2(lo01, lo23);
        }
        __syncthreads();

        // ---- Phase 1: GEMM1 (32 x 512, K=64), split-bf16 mma ----
        {
            const int r0 = rt * 16;
            uint32_t ah[4][4], al[4][4];
            #pragma unroll
            for (int ks = 0; ks < 4; ks++) {
                const int kb = ks * 16 + tg * 2;
                ah[ks][0] = *(const uint32_t*)&XS[(r0 + g) * EMB_S + kb];
                ah[ks][1] = *(const uint32_t*)&XS[(r0 + g + 8) * EMB_S + kb];
                ah[ks][2] = *(const uint32_t*)&XS[(r0 + g) * EMB_S + kb + 8];
                ah[ks][3] = *(const uint32_t*)&XS[(r0 + g + 8) * EMB_S + kb + 8];
                al[ks][0] = *(const uint32_t*)&XL[(r0 + g) * EMB_S + kb];
                al[ks][1] = *(const uint32_t*)&XL[(r0 + g + 8) * EMB_S + kb];
                al[ks][2] = *(const uint32_t*)&XL[(r0 + g) * EMB_S + kb + 8];
                al[ks][3] = *(const uint32_t*)&XL[(r0 + g + 8) * EMB_S + kb + 8];
            }
            #pragma unroll
            for (int tt = 0; tt < 16; tt++) {
                const int n0 = cb * 128 + tt * 8;
                float c[4] = {0.f, 0.f, 0.f, 0.f};
                #pragma unroll
                for (int ks = 0; ks < 4; ks++) {
                    const int kb = ks * 16 + tg * 2;
                    uint32_t bh[2], bl[2];
                    bh[0] = *(const uint32_t*)&EH[(n0 + g) * EMB_S + kb];
                    bh[1] = *(const uint32_t*)&EH[(n0 + g) * EMB_S + kb + 8];
                    bl[0] = *(const uint32_t*)&EL[(n0 + g) * EMB_S + kb];
                    bl[1] = *(const uint32_t*)&EL[(n0 + g) * EMB_S + kb + 8];
                    mma16816(c, ah[ks], bh);
                    mma16816(c, ah[ks], bl);
                    mma16816(c, al[ks], bh);
                }
                const int col = n0 + tg * 2;
                LS[(r0 + g) * LS_S + col]         = 2.f * c[0] - ESQ[col];
                LS[(r0 + g) * LS_S + col + 1]     = 2.f * c[1] - ESQ[col + 1];
                LS[(r0 + g + 8) * LS_S + col]     = 2.f * c[2] - ESQ[col];
                LS[(r0 + g + 8) * LS_S + col + 1] = 2.f * c[3] - ESQ[col + 1];
            }
        }
        __syncthreads();

        // ---- Phase 2: softmax, ret_logits, KL, gumbel softmax, samples ----
        {
            float rowacc[16];
            #pragma unroll
            for (int i = 0; i < 16; i++) rowacc[i] = 0.f;

            const float* urow0 = u + ((size_t)n * BQ + b0 + w * 4) * MQ;
            float ur[16];
            #pragma unroll
            for (int i = 0; i < 16; i++) ur[i] = __ldcs(&urow0[lane + i * 32]);

            for (int rr = 0; rr < 4; rr++) {
                const int r = w * 4 + rr;
                const size_t brow = (size_t)b0 + r;

                float gmb[16];
                #pragma unroll
                for (int i = 0; i < 16; i++) gmb[i] = -__logf(-__logf(ur[i]));

                if (rr < 3) {
                    const float* unext = urow0 + (size_t)(rr + 1) * MQ;
                    #pragma unroll
                    for (int i = 0; i < 16; i++) ur[i] = __ldcs(&unext[lane + i * 32]);
                }

                float l[16];
                #pragma unroll
                for (int i = 0; i < 16; i++) l[i] = LS[r * LS_S + lane + i * 32];

                float t2[16];
                #pragma unroll
                for (int i = 0; i < 16; i++) t2[i] = (l[i] + gmb[i]) * invtau;

                float mx = l[0];
                #pragma unroll
                for (int i = 1; i < 16; i++) mx = fmaxf(mx, l[i]);
                mx = wredmax(mx);

                float mx2 = t2[0];
                #pragma unroll
                for (int i = 1; i < 16; i++) mx2 = fmaxf(mx2, t2[i]);
                mx2 = wredmax(mx2);

                float s1l = 0.f, stfl = 0.f;
                #pragma unroll
                for (int i = 0; i < 16; i++) {
                    const float f = l[i] - mx;
                    const float tv = exp_taylor9(f);
                    s1l += tv;
                    stfl = fmaf(tv, f, stfl);
                }

                float s2l = 0.f;
                #pragma unroll
                for (int i = 0; i < 16; i++) { t2[i] = __expf(t2[i] - mx2); s2l += t2[i]; }

                const float s1  = wredsum(s1l);
                const float stf = wredsum(stfl);
                const float inv2 = 1.0f / wredsum(s2l);

                const float lg1p = log1pf(fmaf(s1, 1.0f / 512.0f, -1.0f));
                const float logZ = mx + LOGM + lg1p;
                kl_acc += stf / s1 - lg1p;   // KL_row (identical across lanes)

                float* outlp = out + OFF_LOGITS + (brow * NQ + n) * MQ;
                #pragma unroll
                for (int i = 0; i < 16; i++) {
                    __stcs(&outlp[lane + i * 32], l[i] - logZ);
                }

                uint32_t* SSM = (uint32_t*)LS;
                #pragma unroll
                for (int i = 0; i < 16; i++) {
                    const float s = t2[i] * inv2;
                    rowacc[i] += s;
                    __nv_bfloat16 h = __float2bfloat16(s);
                    float lo = s - __bfloat162float(h);
                    __nv_bfloat16 hl = __float2bfloat16(lo);
                    uint32_t pk = (uint32_t)__bfloat16_as_ushort(h) |
                                  ((uint32_t)__bfloat16_as_ushort(hl) << 16);
                    SSM[r * LS_S + lane + i * 32] = pk;
                }
            }
            #pragma unroll
            for (int i = 0; i < 16; i++) atomicAdd(&AVG[lane + i * 32], rowacc[i]);
        }
        __syncthreads();

        // ---- Phase 3: GEMM2 quantized = samples @ emb (proven scalar path) ----
        {
            const uint32_t* SSM = (const uint32_t*)LS;
            const uint16_t* EH16 = (const uint16_t*)EH;
            const uint16_t* EL16 = (const uint16_t*)EL;
            const int ra  = rt * 16 + g;
            float c0[4] = {0.f, 0.f, 0.f, 0.f};
            float c1[4] = {0.f, 0.f, 0.f, 0.f};

            #pragma unroll 4
            for (int ks = 0; ks < 32; ks++) {
                const int kb = ks * 16 + tg * 2;
                uint32_t ah[4], al[4];
                #pragma unroll
                for (int j = 0; j < 4; j++) {
                    const int row = ra + (j & 1) * 8;
                    const int kk  = kb + (j >> 1) * 8;
                    const uint32_t p0 = SSM[row * LS_S + kk];
                    const uint32_t p1 = SSM[row * LS_S + kk + 1];
                    ah[j] = __byte_perm(p0, p1, 0x5410);   // hi halves
                    al[j] = __byte_perm(p0, p1, 0x7632);   // lo halves
                }
                #pragma unroll
                for (int dt = 0; dt < 2; dt++) {
                    const int dcol = (dt0 + dt) * 8 + g;
                    uint32_t bh[2], bl[2];
                    bh[0] = (uint32_t)EH16[kb * EMB_S + dcol]       | ((uint32_t)EH16[(kb + 1) * EMB_S + dcol] << 16);
                    bh[1] = (uint32_t)EH16[(kb + 8) * EMB_S + dcol] | ((uint32_t)EH16[(kb + 9) * EMB_S + dcol] << 16);
                    bl[0] = (uint32_t)EL16[kb * EMB_S + dcol]       | ((uint32_t)EL16[(kb + 1) * EMB_S + dcol] << 16);
                    bl[1] = (uint32_t)EL16[(kb + 8) * EMB_S + dcol] | ((uint32_t)EL16[(kb + 9) * EMB_S + dcol] << 16);
                    float* cc = dt ? c1 : c0;
                    mma16816(cc, ah, bh);
                    mma16816(cc, ah, bl);
                    mma16816(cc, al, bh);
                }
            }
            #pragma unroll
            for (int dt = 0; dt < 2; dt++) {
                const float* cc = dt ? c1 : c0;
                const int dcol = (dt0 + dt) * 8 + tg * 2;
                const size_t base0 = ((size_t)(b0 + ra) * NQ + n) * DQ + dcol;
                const size_t base1 = ((size_t)(b0 + ra + 8) * NQ + n) * DQ + dcol;
                __stcs(&out[base0],     cc[0]);
                __stcs(&out[base0 + 1], cc[1]);
                __stcs(&out[base1],     cc[2]);
                __stcs(&out[base1 + 1], cc[3]);
            }
        }
        __syncthreads();
    }

    // ---- flush KL + avg_probs ----
    if (lane == 0) RED[w] = kl_acc;
    __syncthreads();
    if (tid == 0) {
        float s = 0.f;
        #pragma unroll
        for (int i = 0; i < 8; i++) s += RED[i];
        atomicAdd(&g_kl, s);
    }
    for (int i = tid; i < MQ; i += THREADS) atomicAdd(&g_avg[n * MQ + i], AVG[i]);
}

// ---------------------------------------------------------------------------
__global__ void vq_final(float* __restrict__ out) {
    const int tid = threadIdx.x;
    const int w = tid >> 5, lane = tid & 31;
    __shared__ float red[8];
    if (w < 8) {
        float acc = 0.f;
        #pragma unroll
        for (int i = 0; i < 16; i++) {
            float a = g_avg[w * MQ + lane + i * 32] * (1.0f / (float)BQ);
            acc = fmaf(a, __logf(a + 1e-10f), acc);
        }
        acc = wredsum(acc);
        if (lane == 0) red[w] = acc;
    }
    __syncthreads();
    if (tid == 0) {
        float s = 0.f;
        #pragma unroll
        for (int i = 0; i < 8; i++) s += __expf(-red[i]);
        out[OFF_PPL] = s;
        out[OFF_KL]  = g_kl * (1.0f / (float)BQ);
    }
}

extern "C" void kernel_launch(void* const* d_in, const int* in_sizes, int n_in,
                              void* d_out, int out_size) {
    const float* x   = (const float*)d_in[0];
    const float* emb = (const float*)d_in[1];
    const float* u   = (const float*)d_in[2];
    const float* tau = (const float*)d_in[3];
    float* out = (float*)d_out;

    cudaFuncSetAttribute(vq_main, cudaFuncAttributeMaxDynamicSharedMemorySize, SMEM_BYTES);

    vq_init<<<NQ * MQ / 8, 256>>>(emb);
    vq_main<<<dim3(BQ / (BT * TILES), NQ, 1), THREADS, SMEM_BYTES>>>(x, emb, u, tau, out);
    vq_final<<<1, 256>>>(out);
}